// round 12
// baseline (speedup 1.0000x reference)
#include <cuda_runtime.h>
#include <cuda_bf16.h>
#include <math.h>
#include <stdint.h>

#define Bn   32
#define Sn   512
#define Dn   1024
#define Hn   16
#define DKn  64
#define BH   (Bn*Hn)                 // 512
#define Mtot (Bn*Sn)                 // 16384
#define CTX_ELEMS (Bn*Sn*Dn)         // 16,777,216
#define ATT_ELEMS ((size_t)Bn*Hn*Sn*Sn) // 134,217,728

// Scratch (allocation-free per harness rules)
__device__ float g_v[CTX_ELEMS];
__device__ float g_part[(size_t)BH*Sn*8];
__device__ float g_attn_fallback[ATT_ELEMS];
// bf16 hi/lo splits
__device__ __nv_bfloat16 g_xb0[CTX_ELEMS];
__device__ __nv_bfloat16 g_xb1[CTX_ELEMS];
__device__ __nv_bfloat16 g_wb0[3*Dn*Dn];
__device__ __nv_bfloat16 g_wb1[3*Dn*Dn];
__device__ __nv_bfloat16 g_qb0[CTX_ELEMS];
__device__ __nv_bfloat16 g_qb1[CTX_ELEMS];
__device__ __nv_bfloat16 g_kb0[CTX_ELEMS];
__device__ __nv_bfloat16 g_kb1[CTX_ELEMS];
__device__ __nv_bfloat16 g_vt0[CTX_ELEMS];   // V^T: [bh][dk=64][s=512]
__device__ __nv_bfloat16 g_vt1[CTX_ELEMS];

// ---------------- mma.sync bf16 (non-'a' tensor path, works on sm_103) -----
__device__ __forceinline__ void mma_bf16(float4& d, const uint32_t* a,
                                         uint32_t b0, uint32_t b1) {
    asm volatile(
        "mma.sync.aligned.m16n8k16.row.col.f32.bf16.bf16.f32 "
        "{%0,%1,%2,%3},{%4,%5,%6,%7},{%8,%9},{%0,%1,%2,%3};"
        : "+f"(d.x), "+f"(d.y), "+f"(d.z), "+f"(d.w)
        : "r"(a[0]), "r"(a[1]), "r"(a[2]), "r"(a[3]), "r"(b0), "r"(b1));
}

__device__ __forceinline__ void bsplit(float v, __nv_bfloat16& h, __nv_bfloat16& l) {
    h = __float2bfloat16(v);
    l = __float2bfloat16(v - __bfloat162float(h));
}
__device__ __forceinline__ uint32_t packbf(__nv_bfloat16 a, __nv_bfloat16 b) {
    __nv_bfloat162 t(a, b);
    return *(uint32_t*)&t;
}

// ---------------------------------------------------------------------------
// prep: bf16 hi/lo splits of X and the 3 weight matrices (single kernel)
// ---------------------------------------------------------------------------
#define XF4 (CTX_ELEMS/4)            // 4,194,304 float4 in X
#define WF4 (3*Dn*Dn/4)              // 786,432 float4 in W

__global__ __launch_bounds__(256) void prep_kernel(
    const float* __restrict__ X,
    const float* __restrict__ Wq, const float* __restrict__ Wk, const float* __restrict__ Wv)
{
    size_t i = (size_t)blockIdx.x * 256 + threadIdx.x;
    if (i < XF4) {
        float4 v = ((const float4*)X)[i];
        float f[4] = {v.x, v.y, v.z, v.w};
        __nv_bfloat16 b0[4], b1[4];
#pragma unroll
        for (int k = 0; k < 4; k++) bsplit(f[k], b0[k], b1[k]);
        ((uint32_t*)g_xb0)[i*2]   = packbf(b0[0], b0[1]);
        ((uint32_t*)g_xb0)[i*2+1] = packbf(b0[2], b0[3]);
        ((uint32_t*)g_xb1)[i*2]   = packbf(b1[0], b1[1]);
        ((uint32_t*)g_xb1)[i*2+1] = packbf(b1[2], b1[3]);
    } else {
        size_t j = i - XF4;
        if (j >= WF4) return;
        int z = (int)(j >> 18);
        const float* src = (z == 0) ? Wq : (z == 1) ? Wk : Wv;
        float4 v = ((const float4*)src)[j & 262143];
        float f[4] = {v.x, v.y, v.z, v.w};
        __nv_bfloat16 b0[4], b1[4];
#pragma unroll
        for (int k = 0; k < 4; k++) bsplit(f[k], b0[k], b1[k]);
        ((uint32_t*)g_wb0)[j*2]   = packbf(b0[0], b0[1]);
        ((uint32_t*)g_wb0)[j*2+1] = packbf(b0[2], b0[3]);
        ((uint32_t*)g_wb1)[j*2]   = packbf(b1[0], b1[1]);
        ((uint32_t*)g_wb1)[j*2+1] = packbf(b1[2], b1[3]);
    }
}

// ---------------------------------------------------------------------------
// QKV projection via mma.sync bf16x3: C = X @ W^T + bias
// Dead K/V tiles (batch-local row start >= length[b]) early-exit.
// ---------------------------------------------------------------------------
#define SA 20   // smem row stride in words

__global__ __launch_bounds__(256, 2) void qkv_mma_kernel(
    const float* __restrict__ bq, const float* __restrict__ bk, const float* __restrict__ bv,
    const int* __restrict__ length)
{
    __shared__ uint32_t As[2][128*SA];
    __shared__ uint32_t Bs[2][128*SA];

    const int tid  = threadIdx.x;
    const int wid  = tid >> 5;
    const int lane = tid & 31;
    const int gid  = lane >> 2;
    const int tig  = lane & 3;
    const int wm   = wid >> 1;
    const int wn   = wid & 1;
    const int z    = blockIdx.z;
    const int bm   = blockIdx.y * 128;
    const int bn   = blockIdx.x * 128;

    if (z >= 1) {
        if ((bm & 511) >= length[bm >> 9]) return;
    }

    const size_t zoff = (size_t)z * Dn * Dn;
    const __nv_bfloat16* w0p = g_wb0 + zoff;
    const __nv_bfloat16* w1p = g_wb1 + zoff;

    const int r0 = tid >> 3;
    const int c4 = tid & 7;

    float4 acc[2][8];
#pragma unroll
    for (int mt = 0; mt < 2; mt++)
#pragma unroll
        for (int nt = 0; nt < 8; nt++) acc[mt][nt] = make_float4(0.f, 0.f, 0.f, 0.f);

    uint2 areg[4], breg[4];
    {
        const __nv_bfloat16* a = g_xb0 + (size_t)bm * Dn;
        const __nv_bfloat16* w = w0p   + (size_t)bn * Dn;
#pragma unroll
        for (int j = 0; j < 4; j++) {
            int row = r0 + j*32;
            areg[j] = *(const uint2*)(a + (size_t)row*Dn + c4*4);
            breg[j] = *(const uint2*)(w + (size_t)row*Dn + c4*4);
        }
#pragma unroll
        for (int j = 0; j < 4; j++) {
            int row = r0 + j*32;
            int wo = row*SA + c4*2;
            *(uint2*)&As[0][wo] = areg[j];
            *(uint2*)&Bs[0][wo] = breg[j];
        }
    }
    __syncthreads();

    for (int it = 0; it < 96; it++) {
        const int cur = it & 1;
        if (it + 1 < 96) {
            int p  = (it + 1) >> 5;
            int kc = ((it + 1) & 31) * 32;
            const __nv_bfloat16* a = ((p == 2) ? g_xb1 : g_xb0) + (size_t)bm * Dn + kc;
            const __nv_bfloat16* w = ((p == 1) ? w1p  : w0p  ) + (size_t)bn * Dn + kc;
#pragma unroll
            for (int j = 0; j < 4; j++) {
                int row = r0 + j*32;
                areg[j] = *(const uint2*)(a + (size_t)row*Dn + c4*4);
                breg[j] = *(const uint2*)(w + (size_t)row*Dn + c4*4);
            }
        }
#pragma unroll
        for (int s = 0; s < 2; s++) {
            uint32_t af[2][4];
#pragma unroll
            for (int mt = 0; mt < 2; mt++) {
                int base = (wm*32 + mt*16 + gid)*SA + s*8 + tig;
                af[mt][0] = As[cur][base];
                af[mt][1] = As[cur][base + 8*SA];
                af[mt][2] = As[cur][base + 4];
                af[mt][3] = As[cur][base + 8*SA + 4];
            }
#pragma unroll
            for (int nt = 0; nt < 8; nt++) {
                int nb = (wn*64 + nt*8 + gid)*SA + s*8 + tig;
                uint32_t b0 = Bs[cur][nb];
                uint32_t b1 = Bs[cur][nb + 4];
                mma_bf16(acc[0][nt], af[0], b0, b1);
                mma_bf16(acc[1][nt], af[1], b0, b1);
            }
        }
        if (it + 1 < 96) {
            const int nxt = (it + 1) & 1;
#pragma unroll
            for (int j = 0; j < 4; j++) {
                int row = r0 + j*32;
                int wo = row*SA + c4*2;
                *(uint2*)&As[nxt][wo] = areg[j];
                *(uint2*)&Bs[nxt][wo] = breg[j];
            }
            __syncthreads();
        }
    }

    const float* bias = (z == 0) ? bq : (z == 1) ? bk : bv;
    if (z == 2) {
#pragma unroll
        for (int mt = 0; mt < 2; mt++) {
            int rowa = bm + wm*32 + mt*16 + gid;
            int rowb = rowa + 8;
            int ba = rowa >> 9, sa = rowa & 511;
            int bb2 = rowb >> 9, sb = rowb & 511;
#pragma unroll
            for (int nt = 0; nt < 8; nt++) {
                int feat = bn + wn*64 + nt*8 + tig*2;
                int h = feat >> 6, dk = feat & 63;
                float2 bv2 = *(const float2*)&bias[feat];
                float2 v0 = make_float2(acc[mt][nt].x + bv2.x, acc[mt][nt].y + bv2.y);
                float2 v1 = make_float2(acc[mt][nt].z + bv2.x, acc[mt][nt].w + bv2.y);
                *(float2*)&g_v[((size_t)((ba *Hn + h)*Sn + sa))*DKn + dk] = v0;
                *(float2*)&g_v[((size_t)((bb2*Hn + h)*Sn + sb))*DKn + dk] = v1;
            }
        }
    } else {
        __nv_bfloat16* o0 = (z == 0) ? g_qb0 : g_kb0;
        __nv_bfloat16* o1 = (z == 0) ? g_qb1 : g_kb1;
#pragma unroll
        for (int mt = 0; mt < 2; mt++) {
            int rowa = bm + wm*32 + mt*16 + gid;
            int rowb = rowa + 8;
            int ba = rowa >> 9, sa = rowa & 511;
            int bb2 = rowb >> 9, sb = rowb & 511;
#pragma unroll
            for (int nt = 0; nt < 8; nt++) {
                int feat = bn + wn*64 + nt*8 + tig*2;
                int h = feat >> 6, dk = feat & 63;
                float2 bv2 = *(const float2*)&bias[feat];
                float vx = acc[mt][nt].x + bv2.x, vy = acc[mt][nt].y + bv2.y;
                float vz = acc[mt][nt].z + bv2.x, vw = acc[mt][nt].w + bv2.y;
                __nv_bfloat16 hx,lx,hy,ly,hz,lz,hw,lw;
                bsplit(vx,hx,lx); bsplit(vy,hy,ly); bsplit(vz,hz,lz); bsplit(vw,hw,lw);
                size_t ia = ((size_t)((ba *Hn + h)*Sn + sa))*DKn + dk;
                size_t ib = ((size_t)((bb2*Hn + h)*Sn + sb))*DKn + dk;
                *(uint32_t*)&o0[ia] = packbf(hx,hy);
                *(uint32_t*)&o1[ia] = packbf(lx,ly);
                *(uint32_t*)&o0[ib] = packbf(hz,hw);
                *(uint32_t*)&o1[ib] = packbf(lz,lw);
            }
        }
    }
}

// ---------------------------------------------------------------------------
// vtrans: g_v fp32 [bh][s][64] -> bf16 hi/lo V^T [bh][64][512]
// ---------------------------------------------------------------------------
__global__ __launch_bounds__(256) void vtrans_kernel(const int* __restrict__ length)
{
    const int bh = blockIdx.y;
    const int s0 = blockIdx.x * 64;
    {
        int len = length[bh >> 4];
        int kmax = (len + 31) & ~31; if (kmax > Sn) kmax = Sn;
        if (s0 >= kmax) return;
    }
    __shared__ float T[64][65];
    const int tid = threadIdx.x;
#pragma unroll
    for (int j = 0; j < 4; j++) {
        int f = tid + j*256;
        int row = f >> 4, cc = (f & 15) * 4;
        float4 v = *(const float4*)&g_v[((size_t)bh*Sn + s0 + row)*DKn + cc];
        T[row][cc] = v.x; T[row][cc+1] = v.y; T[row][cc+2] = v.z; T[row][cc+3] = v.w;
    }
    __syncthreads();
#pragma unroll
    for (int j = 0; j < 8; j++) {
        int g = tid + j*256;
        int dk = g >> 5, sc = (g & 31) * 2;
        float va = T[sc][dk], vb = T[sc+1][dk];
        __nv_bfloat16 ha,la,hb,lb;
        bsplit(va,ha,la); bsplit(vb,hb,lb);
        size_t idx = ((size_t)bh*DKn + dk)*Sn + s0 + sc;
        *(uint32_t*)&g_vt0[idx] = packbf(ha,hb);
        *(uint32_t*)&g_vt1[idx] = packbf(la,lb);
    }
}

// ---------------------------------------------------------------------------
// scores via mma: E[q][k] = __expf((q·k)/8)*mask.
// 64q x 128k tile per block (warp tile 16x64, acc=32 regs) -> 3 CTAs/SM.
// Fully-masked tiles short-circuit to zero-fill.
// ---------------------------------------------------------------------------
__global__ __launch_bounds__(256, 3) void scores_mma_kernel(
    const int* __restrict__ length, float* __restrict__ attn)
{
    __shared__ uint32_t As[2][64*SA];     // q tile: 64 rows x 32 bf16
    __shared__ uint32_t Bs[2][128*SA];    // k tile: 128 rows x 32 bf16

    const int tid  = threadIdx.x;
    const int wid  = tid >> 5;
    const int lane = tid & 31;
    const int gid  = lane >> 2;
    const int tig  = lane & 3;
    const int wm   = wid >> 1;            // 0..3: 16 q-rows each
    const int wn   = wid & 1;             // 0..1: 64 k-cols each
    const int bh = blockIdx.z;
    const int b  = bh >> 4;
    const int q0 = blockIdx.y * 64;
    const int k0 = blockIdx.x * 128;

    const int len = length[b];

    if (k0 >= len) {
        float4 z4 = make_float4(0.f, 0.f, 0.f, 0.f);
#pragma unroll
        for (int j = 0; j < 8; j++) {
            int f = tid + j*256;              // 2048 float4 sites (64x128)
            int row = f >> 5, cc = (f & 31) * 4;
            *(float4*)&attn[((size_t)bh*Sn + q0 + row)*Sn + k0 + cc] = z4;
        }
        if (tid < 64) {
            size_t pb = ((size_t)bh*Sn + q0 + tid)*8 + blockIdx.x*2;
            g_part[pb]     = 0.f;
            g_part[pb + 1] = 0.f;
        }
        return;
    }

    const __nv_bfloat16* qs[2] = { g_qb0 + ((size_t)bh*Sn + q0)*DKn,
                                   g_qb1 + ((size_t)bh*Sn + q0)*DKn };
    const __nv_bfloat16* ks[2] = { g_kb0 + ((size_t)bh*Sn + k0)*DKn,
                                   g_kb1 + ((size_t)bh*Sn + k0)*DKn };
    const int pa[3] = {0, 0, 1};
    const int pb3[3] = {0, 1, 0};

    float4 acc[8];
#pragma unroll
    for (int nt = 0; nt < 8; nt++) acc[nt] = make_float4(0.f, 0.f, 0.f, 0.f);

    const int ra = tid >> 2;        // A loader: 64 rows, 4 threads/row... (use f-index below)
    uint2 areg[2], breg[4];
    {
#pragma unroll
        for (int j = 0; j < 2; j++) {
            int f = tid + j*256;            // 512 uint2 (64 rows x 8)
            int row = f >> 3, c2 = f & 7;
            areg[j] = *(const uint2*)(qs[0] + (size_t)row*DKn + c2*4);
        }
#pragma unroll
        for (int j = 0; j < 4; j++) {
            int f = tid + j*256;            // 1024 uint2 (128 rows x 8)
            int row = f >> 3, c2 = f & 7;
            breg[j] = *(const uint2*)(ks[0] + (size_t)row*DKn + c2*4);
        }
#pragma unroll
        for (int j = 0; j < 2; j++) {
            int f = tid + j*256;
            int row = f >> 3, c2 = f & 7;
            *(uint2*)&As[0][row*SA + c2*2] = areg[j];
        }
#pragma unroll
        for (int j = 0; j < 4; j++) {
            int f = tid + j*256;
            int row = f >> 3, c2 = f & 7;
            *(uint2*)&Bs[0][row*SA + c2*2] = breg[j];
        }
    }
    __syncthreads();

    for (int it = 0; it < 6; it++) {
        const int cur = it & 1;
        if (it + 1 < 6) {
            int p  = (it + 1) >> 1;
            int kc = ((it + 1) & 1) * 32;
            const __nv_bfloat16* a = qs[pa[p]] + kc;
            const __nv_bfloat16* w = ks[pb3[p]] + kc;
#pragma unroll
            for (int j = 0; j < 2; j++) {
                int f = tid + j*256;
                int row = f >> 3, c2 = f & 7;
                areg[j] = *(const uint2*)(a + (size_t)row*DKn + c2*4);
            }
#pragma unroll
            for (int j = 0; j < 4; j++) {
                int f = tid + j*256;
                int row = f >> 3, c2 = f & 7;
                breg[j] = *(const uint2*)(w + (size_t)row*DKn + c2*4);
            }
        }
#pragma unroll
        for (int s = 0; s < 2; s++) {
            uint32_t af[4];
            int base = (wm*16 + gid)*SA + s*8 + tig;
            af[0] = As[cur][base];
            af[1] = As[cur][base + 8*SA];
            af[2] = As[cur][base + 4];
            af[3] = As[cur][base + 8*SA + 4];
#pragma unroll
            for (int nt = 0; nt < 8; nt++) {
                int nb = (wn*64 + nt*8 + gid)*SA + s*8 + tig;
                mma_bf16(acc[nt], af, Bs[cur][nb], Bs[cur][nb + 4]);
            }
        }
        if (it + 1 < 6) {
            const int nxt = (it + 1) & 1;
#pragma unroll
            for (int j = 0; j < 2; j++) {
                int f = tid + j*256;
                int row = f >> 3, c2 = f & 7;
                *(uint2*)&As[nxt][row*SA + c2*2] = areg[j];
            }
#pragma unroll
            for (int j = 0; j < 4; j++) {
                int f = tid + j*256;
                int row = f >> 3, c2 = f & 7;
                *(uint2*)&Bs[nxt][row*SA + c2*2] = breg[j];
            }
            __syncthreads();
        }
    }

    // epilogue: exp + mask + write + row partials
    {
        int sa = q0 + wm*16 + gid;
        int sb = sa + 8;
        float rpa = 0.f, rpb = 0.f;
#pragma unroll
        for (int nt = 0; nt < 8; nt++) {
            int kc0 = k0 + wn*64 + nt*8 + tig*2;
            float4 a = acc[nt];
            float ex = (kc0   < len) ? __expf(a.x * 0.125f) : 0.f;
            float ey = (kc0+1 < len) ? __expf(a.y * 0.125f) : 0.f;
            float ez = (kc0   < len) ? __expf(a.z * 0.125f) : 0.f;
            float ew = (kc0+1 < len) ? __expf(a.w * 0.125f) : 0.f;
            *(float2*)&attn[((size_t)bh*Sn + sa)*Sn + kc0] = make_float2(ex, ey);
            *(float2*)&attn[((size_t)bh*Sn + sb)*Sn + kc0] = make_float2(ez, ew);
            rpa += ex + ey;
            rpb += ez + ew;
        }
        rpa += __shfl_xor_sync(0xffffffffu, rpa, 1);
        rpa += __shfl_xor_sync(0xffffffffu, rpa, 2);
        rpb += __shfl_xor_sync(0xffffffffu, rpb, 1);
        rpb += __shfl_xor_sync(0xffffffffu, rpb, 2);
        if (tig == 0) {
            g_part[((size_t)bh*Sn + sa)*8 + blockIdx.x*2 + wn] = rpa;
            g_part[((size_t)bh*Sn + sb)*8 + blockIdx.x*2 + wn] = rpb;
        }
    }
}

// ---------------------------------------------------------------------------
// av via mma (R10 version): ctx = (E @ V) * inv. K bounded by length[b].
// Normalizes attn in place. Register prefetch hides gmem latency behind mma.
// ---------------------------------------------------------------------------
__global__ __launch_bounds__(256, 2) void av_mma_kernel(
    const int* __restrict__ length, float* __restrict__ attn, float* __restrict__ ctx)
{
    __shared__ uint32_t As0[128*SA];
    __shared__ uint32_t As1[128*SA];
    __shared__ uint32_t Bs0[64*SA];
    __shared__ uint32_t Bs1[64*SA];
    __shared__ float invS[128];

    const int tid  = threadIdx.x;
    const int wid  = tid >> 5;
    const int lane = tid & 31;
    const int gid  = lane >> 2;
    const int tig  = lane & 3;
    const int bh = blockIdx.y;
    const int b  = bh >> 4;
    const int h  = bh & 15;
    const int q0 = blockIdx.x * 128;

    float* Ah = attn + ((size_t)bh*Sn + q0) * Sn;
    const __nv_bfloat16* vt0 = g_vt0 + (size_t)bh * DKn * Sn;
    const __nv_bfloat16* vt1 = g_vt1 + (size_t)bh * DKn * Sn;

    const int len = length[b];
    int kmax = (len + 31) & ~31;
    if (kmax > Sn) kmax = Sn;

    if (tid < 128) {
        const float* pp = &g_part[((size_t)bh*Sn + q0 + tid)*8];
        float4 p0 = *(const float4*)pp;
        float4 p1 = *(const float4*)(pp + 4);
        float s = p0.x + p0.y + p0.z + p0.w + p1.x + p1.y + p1.z + p1.w;
        invS[tid] = 1.0f / (s + 1e-8f);
    }

    float4 accB[8];
#pragma unroll
    for (int nt = 0; nt < 8; nt++) accB[nt] = make_float4(0.f, 0.f, 0.f, 0.f);

    // prefetch kc = 0
    float4 avr[4];
    uint2 b0r[2], b1r[2];
#pragma unroll
    for (int j = 0; j < 4; j++) {
        int f = tid + j*256;
        int row = f >> 3, cc = f & 7;
        avr[j] = *(const float4*)(Ah + (size_t)row*Sn + 0 + cc*4);
    }
#pragma unroll
    for (int j = 0; j < 2; j++) {
        int g = tid + j*256;
        int row = g >> 3, cc = g & 7;
        b0r[j] = *(const uint2*)(vt0 + (size_t)row*Sn + 0 + cc*4);
        b1r[j] = *(const uint2*)(vt1 + (size_t)row*Sn + 0 + cc*4);
    }

    for (int kc = 0; kc < kmax; kc += 32) {
        __syncthreads();   // prev mma done reading smem; invS ready on iter 0
#pragma unroll
        for (int j = 0; j < 4; j++) {
            int f = tid + j*256;
            int row = f >> 3, cc = f & 7;
            float iv = invS[row];
            float4 vv = avr[j];
            vv.x *= iv; vv.y *= iv; vv.z *= iv; vv.w *= iv;
            *(float4*)(Ah + (size_t)row*Sn + kc + cc*4) = vv;
            __nv_bfloat16 h0,l0,h1,l1,h2,l2,h3,l3;
            bsplit(vv.x,h0,l0); bsplit(vv.y,h1,l1); bsplit(vv.z,h2,l2); bsplit(vv.w,h3,l3);
            int wo = row*SA + cc*2;
            As0[wo]   = packbf(h0,h1); As0[wo+1] = packbf(h2,h3);
            As1[wo]   = packbf(l0,l1); As1[wo+1] = packbf(l2,l3);
        }
#pragma unroll
        for (int j = 0; j < 2; j++) {
            int g = tid + j*256;
            int row = g >> 3, cc = g & 7;
            int wo = row*SA + cc*2;
            *(uint2*)&Bs0[wo] = b0r[j];
            *(uint2*)&Bs1[wo] = b1r[j];
        }
        __syncthreads();

        // prefetch next chunk while mma runs
        if (kc + 32 < kmax) {
#pragma unroll
            for (int j = 0; j < 4; j++) {
                int f = tid + j*256;
                int row = f >> 3, cc = f & 7;
                avr[j] = *(const float4*)(Ah + (size_t)row*Sn + kc + 32 + cc*4);
            }
#pragma unroll
            for (int j = 0; j < 2; j++) {
                int g = tid + j*256;
                int row = g >> 3, cc = g & 7;
                b0r[j] = *(const uint2*)(vt0 + (size_t)row*Sn + kc + 32 + cc*4);
                b1r[j] = *(const uint2*)(vt1 + (size_t)row*Sn + kc + 32 + cc*4);
            }
        }

#pragma unroll
        for (int s = 0; s < 2; s++) {
            uint32_t af0[4], af1[4];
            int base = (wid*16 + gid)*SA + s*8 + tig;
            af0[0] = As0[base];        af0[1] = As0[base + 8*SA];
            af0[2] = As0[base + 4];    af0[3] = As0[base + 8*SA + 4];
            af1[0] = As1[base];        af1[1] = As1[base + 8*SA];
            af1[2] = As1[base + 4];    af1[3] = As1[base + 8*SA + 4];
#pragma unroll
            for (int nt = 0; nt < 8; nt++) {
                int nb = (nt*8 + gid)*SA + s*8 + tig;
                uint32_t b00 = Bs0[nb], b01 = Bs0[nb + 4];
                uint32_t b10 = Bs1[nb], b11 = Bs1[nb + 4];
                mma_bf16(accB[nt], af0, b00, b01);   // a0*v0
                mma_bf16(accB[nt], af0, b10, b11);   // a0*v1
                mma_bf16(accB[nt], af1, b00, b01);   // a1*v0
            }
        }
    }

    int sa = q0 + wid*16 + gid;
    int sb = sa + 8;
#pragma unroll
    for (int nt = 0; nt < 8; nt++) {
        int dk = nt*8 + tig*2;
        *(float2*)&ctx[((size_t)(b*Sn + sa))*Dn + h*DKn + dk] = make_float2(accB[nt].x, accB[nt].y);
        *(float2*)&ctx[((size_t)(b*Sn + sb))*Dn + h*DKn + dk] = make_float2(accB[nt].z, accB[nt].w);
    }
}

// ---------------------------------------------------------------------------
extern "C" void kernel_launch(void* const* d_in, const int* in_sizes, int n_in,
                              void* d_out, int out_size)
{
    const float* Q   = (const float*)d_in[0];
    const float* Wq  = (const float*)d_in[1];
    const float* bq  = (const float*)d_in[2];
    const float* Wk  = (const float*)d_in[3];
    const float* bk  = (const float*)d_in[4];
    const float* Wv  = (const float*)d_in[5];
    const float* bv  = (const float*)d_in[6];
    const int*   len = (const int*)d_in[7];

    float* ctx = (float*)d_out;
    float* attn;
    if ((size_t)out_size >= (size_t)CTX_ELEMS + ATT_ELEMS) {
        attn = ctx + CTX_ELEMS;   // tuple output: [context | attn]
    } else {
        void* p = nullptr;
        cudaGetSymbolAddress(&p, g_attn_fallback);
        attn = (float*)p;
    }

    // 0) bf16 hi/lo splits of inputs (single kernel)
    prep_kernel<<<dim3((XF4 + WF4 + 255)/256), 256>>>(Q, Wq, Wk, Wv);
    // 1) QKV projections (tensor cores); dead K/V tiles skipped
    qkv_mma_kernel<<<dim3(Dn/128, Mtot/128, 3), 256>>>(bq, bk, bv, len);
    // 1b) V^T bf16 splits (tiles beyond length skipped)
    vtrans_kernel<<<dim3(Sn/64, BH), 256>>>(len);
    // 2) scores (tensor cores): 64x128 tiles, 3 CTAs/SM, masked tiles skip
    scores_mma_kernel<<<dim3(Sn/128, Sn/64, BH), 256>>>(len, attn);
    // 3) context = (E @ V) * inv (tensor cores; normalizes attn in place)
    av_mma_kernel<<<dim3(Sn/128, BH), 256>>>(len, attn, ctx);
}

// round 13
// speedup vs baseline: 1.5623x; 1.5623x over previous
#include <cuda_runtime.h>
#include <cuda_bf16.h>
#include <math.h>
#include <stdint.h>

#define Bn   32
#define Sn   512
#define Dn   1024
#define Hn   16
#define DKn  64
#define BH   (Bn*Hn)                 // 512
#define Mtot (Bn*Sn)                 // 16384
#define CTX_ELEMS (Bn*Sn*Dn)         // 16,777,216
#define ATT_ELEMS ((size_t)Bn*Hn*Sn*Sn) // 134,217,728

// Scratch (allocation-free per harness rules)
__device__ float g_v[CTX_ELEMS];
__device__ float g_rowsum[BH*Sn];
__device__ float g_attn_fallback[ATT_ELEMS];
// bf16 hi/lo splits
__device__ __nv_bfloat16 g_xb0[CTX_ELEMS];
__device__ __nv_bfloat16 g_xb1[CTX_ELEMS];
__device__ __nv_bfloat16 g_wb0[3*Dn*Dn];
__device__ __nv_bfloat16 g_wb1[3*Dn*Dn];
__device__ __nv_bfloat16 g_qb0[CTX_ELEMS];
__device__ __nv_bfloat16 g_qb1[CTX_ELEMS];
__device__ __nv_bfloat16 g_kb0[CTX_ELEMS];
__device__ __nv_bfloat16 g_kb1[CTX_ELEMS];
__device__ __nv_bfloat16 g_vt0[CTX_ELEMS];   // V^T: [bh][dk=64][s=512]
__device__ __nv_bfloat16 g_vt1[CTX_ELEMS];

// ---------------- mma.sync bf16 (non-'a' tensor path, works on sm_103) -----
__device__ __forceinline__ void mma_bf16(float4& d, const uint32_t* a,
                                         uint32_t b0, uint32_t b1) {
    asm volatile(
        "mma.sync.aligned.m16n8k16.row.col.f32.bf16.bf16.f32 "
        "{%0,%1,%2,%3},{%4,%5,%6,%7},{%8,%9},{%0,%1,%2,%3};"
        : "+f"(d.x), "+f"(d.y), "+f"(d.z), "+f"(d.w)
        : "r"(a[0]), "r"(a[1]), "r"(a[2]), "r"(a[3]), "r"(b0), "r"(b1));
}

__device__ __forceinline__ void bsplit(float v, __nv_bfloat16& h, __nv_bfloat16& l) {
    h = __float2bfloat16(v);
    l = __float2bfloat16(v - __bfloat162float(h));
}
__device__ __forceinline__ uint32_t packbf(__nv_bfloat16 a, __nv_bfloat16 b) {
    __nv_bfloat162 t(a, b);
    return *(uint32_t*)&t;
}

// ---------------------------------------------------------------------------
// prep: bf16 hi/lo splits of X and the 3 weight matrices (single kernel)
// ---------------------------------------------------------------------------
#define XF4 (CTX_ELEMS/4)            // 4,194,304 float4 in X
#define WF4 (3*Dn*Dn/4)              // 786,432 float4 in W

__global__ __launch_bounds__(256) void prep_kernel(
    const float* __restrict__ X,
    const float* __restrict__ Wq, const float* __restrict__ Wk, const float* __restrict__ Wv)
{
    size_t i = (size_t)blockIdx.x * 256 + threadIdx.x;
    if (i < XF4) {
        float4 v = ((const float4*)X)[i];
        float f[4] = {v.x, v.y, v.z, v.w};
        __nv_bfloat16 b0[4], b1[4];
#pragma unroll
        for (int k = 0; k < 4; k++) bsplit(f[k], b0[k], b1[k]);
        ((uint32_t*)g_xb0)[i*2]   = packbf(b0[0], b0[1]);
        ((uint32_t*)g_xb0)[i*2+1] = packbf(b0[2], b0[3]);
        ((uint32_t*)g_xb1)[i*2]   = packbf(b1[0], b1[1]);
        ((uint32_t*)g_xb1)[i*2+1] = packbf(b1[2], b1[3]);
    } else {
        size_t j = i - XF4;
        if (j >= WF4) return;
        int z = (int)(j >> 18);
        const float* src = (z == 0) ? Wq : (z == 1) ? Wk : Wv;
        float4 v = ((const float4*)src)[j & 262143];
        float f[4] = {v.x, v.y, v.z, v.w};
        __nv_bfloat16 b0[4], b1[4];
#pragma unroll
        for (int k = 0; k < 4; k++) bsplit(f[k], b0[k], b1[k]);
        ((uint32_t*)g_wb0)[j*2]   = packbf(b0[0], b0[1]);
        ((uint32_t*)g_wb0)[j*2+1] = packbf(b0[2], b0[3]);
        ((uint32_t*)g_wb1)[j*2]   = packbf(b1[0], b1[1]);
        ((uint32_t*)g_wb1)[j*2+1] = packbf(b1[2], b1[3]);
    }
}

// ---------------------------------------------------------------------------
// QKV projection via mma.sync bf16x3: C = X @ W^T + bias
// Dead K/V tiles (batch-local row start >= length[b]) early-exit.
// ---------------------------------------------------------------------------
#define SA 20   // smem row stride in words

__global__ __launch_bounds__(256, 2) void qkv_mma_kernel(
    const float* __restrict__ bq, const float* __restrict__ bk, const float* __restrict__ bv,
    const int* __restrict__ length)
{
    __shared__ uint32_t As[2][128*SA];
    __shared__ uint32_t Bs[2][128*SA];

    const int tid  = threadIdx.x;
    const int wid  = tid >> 5;
    const int lane = tid & 31;
    const int gid  = lane >> 2;
    const int tig  = lane & 3;
    const int wm   = wid >> 1;
    const int wn   = wid & 1;
    const int z    = blockIdx.z;
    const int bm   = blockIdx.y * 128;
    const int bn   = blockIdx.x * 128;

    if (z >= 1) {
        if ((bm & 511) >= length[bm >> 9]) return;
    }

    const size_t zoff = (size_t)z * Dn * Dn;
    const __nv_bfloat16* w0p = g_wb0 + zoff;
    const __nv_bfloat16* w1p = g_wb1 + zoff;

    const int r0 = tid >> 3;
    const int c4 = tid & 7;

    float4 acc[2][8];
#pragma unroll
    for (int mt = 0; mt < 2; mt++)
#pragma unroll
        for (int nt = 0; nt < 8; nt++) acc[mt][nt] = make_float4(0.f, 0.f, 0.f, 0.f);

    uint2 areg[4], breg[4];
    {
        const __nv_bfloat16* a = g_xb0 + (size_t)bm * Dn;
        const __nv_bfloat16* w = w0p   + (size_t)bn * Dn;
#pragma unroll
        for (int j = 0; j < 4; j++) {
            int row = r0 + j*32;
            areg[j] = *(const uint2*)(a + (size_t)row*Dn + c4*4);
            breg[j] = *(const uint2*)(w + (size_t)row*Dn + c4*4);
        }
#pragma unroll
        for (int j = 0; j < 4; j++) {
            int row = r0 + j*32;
            int wo = row*SA + c4*2;
            *(uint2*)&As[0][wo] = areg[j];
            *(uint2*)&Bs[0][wo] = breg[j];
        }
    }
    __syncthreads();

    for (int it = 0; it < 96; it++) {
        const int cur = it & 1;
        if (it + 1 < 96) {
            int p  = (it + 1) >> 5;
            int kc = ((it + 1) & 31) * 32;
            const __nv_bfloat16* a = ((p == 2) ? g_xb1 : g_xb0) + (size_t)bm * Dn + kc;
            const __nv_bfloat16* w = ((p == 1) ? w1p  : w0p  ) + (size_t)bn * Dn + kc;
#pragma unroll
            for (int j = 0; j < 4; j++) {
                int row = r0 + j*32;
                areg[j] = *(const uint2*)(a + (size_t)row*Dn + c4*4);
                breg[j] = *(const uint2*)(w + (size_t)row*Dn + c4*4);
            }
        }
#pragma unroll
        for (int s = 0; s < 2; s++) {
            uint32_t af[2][4];
#pragma unroll
            for (int mt = 0; mt < 2; mt++) {
                int base = (wm*32 + mt*16 + gid)*SA + s*8 + tig;
                af[mt][0] = As[cur][base];
                af[mt][1] = As[cur][base + 8*SA];
                af[mt][2] = As[cur][base + 4];
                af[mt][3] = As[cur][base + 8*SA + 4];
            }
#pragma unroll
            for (int nt = 0; nt < 8; nt++) {
                int nb = (wn*64 + nt*8 + gid)*SA + s*8 + tig;
                uint32_t b0 = Bs[cur][nb];
                uint32_t b1 = Bs[cur][nb + 4];
                mma_bf16(acc[0][nt], af[0], b0, b1);
                mma_bf16(acc[1][nt], af[1], b0, b1);
            }
        }
        if (it + 1 < 96) {
            const int nxt = (it + 1) & 1;
#pragma unroll
            for (int j = 0; j < 4; j++) {
                int row = r0 + j*32;
                int wo = row*SA + c4*2;
                *(uint2*)&As[nxt][wo] = areg[j];
                *(uint2*)&Bs[nxt][wo] = breg[j];
            }
            __syncthreads();
        }
    }

    const float* bias = (z == 0) ? bq : (z == 1) ? bk : bv;
    if (z == 2) {
#pragma unroll
        for (int mt = 0; mt < 2; mt++) {
            int rowa = bm + wm*32 + mt*16 + gid;
            int rowb = rowa + 8;
            int ba = rowa >> 9, sa = rowa & 511;
            int bb2 = rowb >> 9, sb = rowb & 511;
#pragma unroll
            for (int nt = 0; nt < 8; nt++) {
                int feat = bn + wn*64 + nt*8 + tig*2;
                int h = feat >> 6, dk = feat & 63;
                float2 bv2 = *(const float2*)&bias[feat];
                float2 v0 = make_float2(acc[mt][nt].x + bv2.x, acc[mt][nt].y + bv2.y);
                float2 v1 = make_float2(acc[mt][nt].z + bv2.x, acc[mt][nt].w + bv2.y);
                *(float2*)&g_v[((size_t)((ba *Hn + h)*Sn + sa))*DKn + dk] = v0;
                *(float2*)&g_v[((size_t)((bb2*Hn + h)*Sn + sb))*DKn + dk] = v1;
            }
        }
    } else {
        __nv_bfloat16* o0 = (z == 0) ? g_qb0 : g_kb0;
        __nv_bfloat16* o1 = (z == 0) ? g_qb1 : g_kb1;
#pragma unroll
        for (int mt = 0; mt < 2; mt++) {
            int rowa = bm + wm*32 + mt*16 + gid;
            int rowb = rowa + 8;
            int ba = rowa >> 9, sa = rowa & 511;
            int bb2 = rowb >> 9, sb = rowb & 511;
#pragma unroll
            for (int nt = 0; nt < 8; nt++) {
                int feat = bn + wn*64 + nt*8 + tig*2;
                int h = feat >> 6, dk = feat & 63;
                float2 bv2 = *(const float2*)&bias[feat];
                float vx = acc[mt][nt].x + bv2.x, vy = acc[mt][nt].y + bv2.y;
                float vz = acc[mt][nt].z + bv2.x, vw = acc[mt][nt].w + bv2.y;
                __nv_bfloat16 hx,lx,hy,ly,hz,lz,hw,lw;
                bsplit(vx,hx,lx); bsplit(vy,hy,ly); bsplit(vz,hz,lz); bsplit(vw,hw,lw);
                size_t ia = ((size_t)((ba *Hn + h)*Sn + sa))*DKn + dk;
                size_t ib = ((size_t)((bb2*Hn + h)*Sn + sb))*DKn + dk;
                *(uint32_t*)&o0[ia] = packbf(hx,hy);
                *(uint32_t*)&o1[ia] = packbf(lx,ly);
                *(uint32_t*)&o0[ib] = packbf(hz,hw);
                *(uint32_t*)&o1[ib] = packbf(lz,lw);
            }
        }
    }
}

// ---------------------------------------------------------------------------
// vtrans: g_v fp32 [bh][s][64] -> bf16 hi/lo V^T [bh][64][512]
// ---------------------------------------------------------------------------
__global__ __launch_bounds__(256) void vtrans_kernel(const int* __restrict__ length)
{
    const int bh = blockIdx.y;
    const int s0 = blockIdx.x * 64;
    {
        int len = length[bh >> 4];
        int kmax = (len + 31) & ~31; if (kmax > Sn) kmax = Sn;
        if (s0 >= kmax) return;
    }
    __shared__ float T[64][65];
    const int tid = threadIdx.x;
#pragma unroll
    for (int j = 0; j < 4; j++) {
        int f = tid + j*256;
        int row = f >> 4, cc = (f & 15) * 4;
        float4 v = *(const float4*)&g_v[((size_t)bh*Sn + s0 + row)*DKn + cc];
        T[row][cc] = v.x; T[row][cc+1] = v.y; T[row][cc+2] = v.z; T[row][cc+3] = v.w;
    }
    __syncthreads();
#pragma unroll
    for (int j = 0; j < 8; j++) {
        int g = tid + j*256;
        int dk = g >> 5, sc = (g & 31) * 2;
        float va = T[sc][dk], vb = T[sc+1][dk];
        __nv_bfloat16 ha,la,hb,lb;
        bsplit(va,ha,la); bsplit(vb,hb,lb);
        size_t idx = ((size_t)bh*DKn + dk)*Sn + s0 + sc;
        *(uint32_t*)&g_vt0[idx] = packbf(ha,hb);
        *(uint32_t*)&g_vt1[idx] = packbf(la,lb);
    }
}

// ---------------------------------------------------------------------------
// scores via mma: one CTA computes a full 128q x 512k row-block:
// nsub = ceil(len/128) active 128-wide k-subtiles processed in a continuous
// double-buffered pipeline (Q loaded once); per-subtile epilogue does
// exp+mask+write and accumulates complete rowsums (written to g_rowsum).
// Trailing masked strips are zero-filled.
// ---------------------------------------------------------------------------
__global__ __launch_bounds__(256, 2) void scores_mma_kernel(
    const int* __restrict__ length, float* __restrict__ attn)
{
    __shared__ uint32_t As[2][128*SA];
    __shared__ uint32_t Bs[2][128*SA];
    __shared__ float rs[128][2];

    const int tid  = threadIdx.x;
    const int wid  = tid >> 5;
    const int lane = tid & 31;
    const int gid  = lane >> 2;
    const int tig  = lane & 3;
    const int wm   = wid >> 1;
    const int wn   = wid & 1;
    const int bh = blockIdx.y;
    const int b  = bh >> 4;
    const int q0 = blockIdx.x * 128;

    const int len = length[b];
    int nsub = (len + 127) >> 7;
    if (nsub > 4) nsub = 4;
    const int total = nsub * 6;

    const int r0 = tid >> 3;
    const int c4 = tid & 7;

    const __nv_bfloat16* qs[2] = { g_qb0 + ((size_t)bh*Sn + q0)*DKn,
                                   g_qb1 + ((size_t)bh*Sn + q0)*DKn };
    const __nv_bfloat16* kb[2] = { g_kb0 + (size_t)bh*Sn*DKn,
                                   g_kb1 + (size_t)bh*Sn*DKn };
    const int pa[3]  = {0, 0, 1};
    const int pb3[3] = {0, 1, 0};

    float4 acc[2][8];
#pragma unroll
    for (int mt = 0; mt < 2; mt++)
#pragma unroll
        for (int nt = 0; nt < 8; nt++) acc[mt][nt] = make_float4(0.f, 0.f, 0.f, 0.f);
    float rp[2][2] = {{0.f, 0.f}, {0.f, 0.f}};

    uint2 areg[4], breg[4];
    // load stage gi=0 (sub 0, product 0, kc 0)
    {
        const __nv_bfloat16* a = qs[0];
        const __nv_bfloat16* w = kb[0];
#pragma unroll
        for (int j = 0; j < 4; j++) {
            int row = r0 + j*32;
            areg[j] = *(const uint2*)(a + (size_t)row*DKn + c4*4);
            breg[j] = *(const uint2*)(w + (size_t)row*DKn + c4*4);
        }
#pragma unroll
        for (int j = 0; j < 4; j++) {
            int row = r0 + j*32;
            int wo = row*SA + c4*2;
            *(uint2*)&As[0][wo] = areg[j];
            *(uint2*)&Bs[0][wo] = breg[j];
        }
    }
    __syncthreads();

    for (int gi = 0; gi < total; gi++) {
        const int cur = gi & 1;
        if (gi + 1 < total) {
            int g1  = gi + 1;
            int sub = g1 / 6;
            int qq  = g1 - sub*6;
            int p   = qq >> 1;
            int kc  = (qq & 1) * 32;
            const __nv_bfloat16* a = qs[pa[p]] + kc;
            const __nv_bfloat16* w = kb[pb3[p]] + (size_t)(sub << 7)*DKn + kc;
#pragma unroll
            for (int j = 0; j < 4; j++) {
                int row = r0 + j*32;
                areg[j] = *(const uint2*)(a + (size_t)row*DKn + c4*4);
                breg[j] = *(const uint2*)(w + (size_t)row*DKn + c4*4);
            }
        }
#pragma unroll
        for (int s = 0; s < 2; s++) {
            uint32_t af[2][4];
#pragma unroll
            for (int mt = 0; mt < 2; mt++) {
                int base = (wm*32 + mt*16 + gid)*SA + s*8 + tig;
                af[mt][0] = As[cur][base];
                af[mt][1] = As[cur][base + 8*SA];
                af[mt][2] = As[cur][base + 4];
                af[mt][3] = As[cur][base + 8*SA + 4];
            }
#pragma unroll
            for (int nt = 0; nt < 8; nt++) {
                int nb = (wn*64 + nt*8 + gid)*SA + s*8 + tig;
                uint32_t b0 = Bs[cur][nb];
                uint32_t b1 = Bs[cur][nb + 4];
                mma_bf16(acc[0][nt], af[0], b0, b1);
                mma_bf16(acc[1][nt], af[1], b0, b1);
            }
        }
        // per-subtile epilogue after its 6th iteration (register-only + gmem)
        if ((gi % 6) == 5) {
            const int k0 = (gi / 6) << 7;
#pragma unroll
            for (int mt = 0; mt < 2; mt++) {
                int sa = q0 + wm*32 + mt*16 + gid;
                int sb = sa + 8;
#pragma unroll
                for (int nt = 0; nt < 8; nt++) {
                    int kc0 = k0 + wn*64 + nt*8 + tig*2;
                    float4 a = acc[mt][nt];
                    float ex = (kc0   < len) ? __expf(a.x * 0.125f) : 0.f;
                    float ey = (kc0+1 < len) ? __expf(a.y * 0.125f) : 0.f;
                    float ez = (kc0   < len) ? __expf(a.z * 0.125f) : 0.f;
                    float ew = (kc0+1 < len) ? __expf(a.w * 0.125f) : 0.f;
                    *(float2*)&attn[((size_t)bh*Sn + sa)*Sn + kc0] = make_float2(ex, ey);
                    *(float2*)&attn[((size_t)bh*Sn + sb)*Sn + kc0] = make_float2(ez, ew);
                    rp[mt][0] += ex + ey;
                    rp[mt][1] += ez + ew;
                    acc[mt][nt] = make_float4(0.f, 0.f, 0.f, 0.f);
                }
            }
        }
        if (gi + 1 < total) {
            const int nxt = (gi + 1) & 1;
#pragma unroll
            for (int j = 0; j < 4; j++) {
                int row = r0 + j*32;
                int wo = row*SA + c4*2;
                *(uint2*)&As[nxt][wo] = areg[j];
                *(uint2*)&Bs[nxt][wo] = breg[j];
            }
            __syncthreads();
        }
    }

    // zero-fill fully masked strips
    for (int sub = nsub; sub < 4; sub++) {
        const int k0 = sub << 7;
        float4 z4 = make_float4(0.f, 0.f, 0.f, 0.f);
#pragma unroll
        for (int j = 0; j < 16; j++) {
            int f = tid + j*256;
            int row = f >> 5, cc = (f & 31) * 4;
            *(float4*)&attn[((size_t)bh*Sn + q0 + row)*Sn + k0 + cc] = z4;
        }
    }

    // complete rowsums -> g_rowsum
#pragma unroll
    for (int mt = 0; mt < 2; mt++) {
        rp[mt][0] += __shfl_xor_sync(0xffffffffu, rp[mt][0], 1);
        rp[mt][0] += __shfl_xor_sync(0xffffffffu, rp[mt][0], 2);
        rp[mt][1] += __shfl_xor_sync(0xffffffffu, rp[mt][1], 1);
        rp[mt][1] += __shfl_xor_sync(0xffffffffu, rp[mt][1], 2);
        if (tig == 0) {
            int ra = wm*32 + mt*16 + gid;
            rs[ra][wn]     = rp[mt][0];
            rs[ra + 8][wn] = rp[mt][1];
        }
    }
    __syncthreads();
    if (tid < 128)
        g_rowsum[(size_t)bh*Sn + q0 + tid] = rs[tid][0] + rs[tid][1];
}

// ---------------------------------------------------------------------------
// av via mma: ctx = (E @ V) * inv. K bounded by length[b]. Normalizes attn
// in place. Register prefetch hides gmem latency behind mma.
// ---------------------------------------------------------------------------
__global__ __launch_bounds__(256, 2) void av_mma_kernel(
    const int* __restrict__ length, float* __restrict__ attn, float* __restrict__ ctx)
{
    __shared__ uint32_t As0[128*SA];
    __shared__ uint32_t As1[128*SA];
    __shared__ uint32_t Bs0[64*SA];
    __shared__ uint32_t Bs1[64*SA];
    __shared__ float invS[128];

    const int tid  = threadIdx.x;
    const int wid  = tid >> 5;
    const int lane = tid & 31;
    const int gid  = lane >> 2;
    const int tig  = lane & 3;
    const int bh = blockIdx.y;
    const int b  = bh >> 4;
    const int h  = bh & 15;
    const int q0 = blockIdx.x * 128;

    float* Ah = attn + ((size_t)bh*Sn + q0) * Sn;
    const __nv_bfloat16* vt0 = g_vt0 + (size_t)bh * DKn * Sn;
    const __nv_bfloat16* vt1 = g_vt1 + (size_t)bh * DKn * Sn;

    const int len = length[b];
    int kmax = (len + 31) & ~31;
    if (kmax > Sn) kmax = Sn;

    if (tid < 128)
        invS[tid] = 1.0f / (g_rowsum[(size_t)bh*Sn + q0 + tid] + 1e-8f);

    float4 accB[8];
#pragma unroll
    for (int nt = 0; nt < 8; nt++) accB[nt] = make_float4(0.f, 0.f, 0.f, 0.f);

    // prefetch kc = 0
    float4 avr[4];
    uint2 b0r[2], b1r[2];
#pragma unroll
    for (int j = 0; j < 4; j++) {
        int f = tid + j*256;
        int row = f >> 3, cc = f & 7;
        avr[j] = *(const float4*)(Ah + (size_t)row*Sn + 0 + cc*4);
    }
#pragma unroll
    for (int j = 0; j < 2; j++) {
        int g = tid + j*256;
        int row = g >> 3, cc = g & 7;
        b0r[j] = *(const uint2*)(vt0 + (size_t)row*Sn + 0 + cc*4);
        b1r[j] = *(const uint2*)(vt1 + (size_t)row*Sn + 0 + cc*4);
    }

    for (int kc = 0; kc < kmax; kc += 32) {
        __syncthreads();   // prev mma done reading smem; invS ready on iter 0
#pragma unroll
        for (int j = 0; j < 4; j++) {
            int f = tid + j*256;
            int row = f >> 3, cc = f & 7;
            float iv = invS[row];
            float4 vv = avr[j];
            vv.x *= iv; vv.y *= iv; vv.z *= iv; vv.w *= iv;
            *(float4*)(Ah + (size_t)row*Sn + kc + cc*4) = vv;
            __nv_bfloat16 h0,l0,h1,l1,h2,l2,h3,l3;
            bsplit(vv.x,h0,l0); bsplit(vv.y,h1,l1); bsplit(vv.z,h2,l2); bsplit(vv.w,h3,l3);
            int wo = row*SA + cc*2;
            As0[wo]   = packbf(h0,h1); As0[wo+1] = packbf(h2,h3);
            As1[wo]   = packbf(l0,l1); As1[wo+1] = packbf(l2,l3);
        }
#pragma unroll
        for (int j = 0; j < 2; j++) {
            int g = tid + j*256;
            int row = g >> 3, cc = g & 7;
            int wo = row*SA + cc*2;
            *(uint2*)&Bs0[wo] = b0r[j];
            *(uint2*)&Bs1[wo] = b1r[j];
        }
        __syncthreads();

        // prefetch next chunk while mma runs
        if (kc + 32 < kmax) {
#pragma unroll
            for (int j = 0; j < 4; j++) {
                int f = tid + j*256;
                int row = f >> 3, cc = f & 7;
                avr[j] = *(const float4*)(Ah + (size_t)row*Sn + kc + 32 + cc*4);
            }
#pragma unroll
            for (int j = 0; j < 2; j++) {
                int g = tid + j*256;
                int row = g >> 3, cc = g & 7;
                b0r[j] = *(const uint2*)(vt0 + (size_t)row*Sn + kc + 32 + cc*4);
                b1r[j] = *(const uint2*)(vt1 + (size_t)row*Sn + kc + 32 + cc*4);
            }
        }

#pragma unroll
        for (int s = 0; s < 2; s++) {
            uint32_t af0[4], af1[4];
            int base = (wid*16 + gid)*SA + s*8 + tig;
            af0[0] = As0[base];        af0[1] = As0[base + 8*SA];
            af0[2] = As0[base + 4];    af0[3] = As0[base + 8*SA + 4];
            af1[0] = As1[base];        af1[1] = As1[base + 8*SA];
            af1[2] = As1[base + 4];    af1[3] = As1[base + 8*SA + 4];
#pragma unroll
            for (int nt = 0; nt < 8; nt++) {
                int nb = (nt*8 + gid)*SA + s*8 + tig;
                uint32_t b00 = Bs0[nb], b01 = Bs0[nb + 4];
                uint32_t b10 = Bs1[nb], b11 = Bs1[nb + 4];
                mma_bf16(accB[nt], af0, b00, b01);   // a0*v0
                mma_bf16(accB[nt], af0, b10, b11);   // a0*v1
                mma_bf16(accB[nt], af1, b00, b01);   // a1*v0
            }
        }
    }

    int sa = q0 + wid*16 + gid;
    int sb = sa + 8;
#pragma unroll
    for (int nt = 0; nt < 8; nt++) {
        int dk = nt*8 + tig*2;
        *(float2*)&ctx[((size_t)(b*Sn + sa))*Dn + h*DKn + dk] = make_float2(accB[nt].x, accB[nt].y);
        *(float2*)&ctx[((size_t)(b*Sn + sb))*Dn + h*DKn + dk] = make_float2(accB[nt].z, accB[nt].w);
    }
}

// ---------------------------------------------------------------------------
extern "C" void kernel_launch(void* const* d_in, const int* in_sizes, int n_in,
                              void* d_out, int out_size)
{
    const float* Q   = (const float*)d_in[0];
    const float* Wq  = (const float*)d_in[1];
    const float* bq  = (const float*)d_in[2];
    const float* Wk  = (const float*)d_in[3];
    const float* bk  = (const float*)d_in[4];
    const float* Wv  = (const float*)d_in[5];
    const float* bv  = (const float*)d_in[6];
    const int*   len = (const int*)d_in[7];

    float* ctx = (float*)d_out;
    float* attn;
    if ((size_t)out_size >= (size_t)CTX_ELEMS + ATT_ELEMS) {
        attn = ctx + CTX_ELEMS;   // tuple output: [context | attn]
    } else {
        void* p = nullptr;
        cudaGetSymbolAddress(&p, g_attn_fallback);
        attn = (float*)p;
    }

    // 0) bf16 hi/lo splits of inputs (single kernel)
    prep_kernel<<<dim3((XF4 + WF4 + 255)/256), 256>>>(Q, Wq, Wk, Wv);
    // 1) QKV projections (tensor cores); dead K/V tiles skipped
    qkv_mma_kernel<<<dim3(Dn/128, Mtot/128, 3), 256>>>(bq, bk, bv, len);
    // 1b) V^T bf16 splits (tiles beyond length skipped)
    vtrans_kernel<<<dim3(Sn/64, BH), 256>>>(len);
    // 2) scores (tensor cores): full 128q x 512k per CTA, complete rowsums
    scores_mma_kernel<<<dim3(Sn/128, BH), 256>>>(len, attn);
    // 3) context = (E @ V) * inv (tensor cores; normalizes attn in place)
    av_mma_kernel<<<dim3(Sn/128, BH), 256>>>(len, attn, ctx);
}

// round 14
// speedup vs baseline: 1.5972x; 1.0223x over previous
#include <cuda_runtime.h>
#include <cuda_bf16.h>
#include <math.h>
#include <stdint.h>

#define Bn   32
#define Sn   512
#define Dn   1024
#define Hn   16
#define DKn  64
#define BH   (Bn*Hn)                 // 512
#define Mtot (Bn*Sn)                 // 16384
#define CTX_ELEMS (Bn*Sn*Dn)         // 16,777,216
#define ATT_ELEMS ((size_t)Bn*Hn*Sn*Sn) // 134,217,728

// Scratch (allocation-free per harness rules)
__device__ float g_v[CTX_ELEMS];
__device__ float g_attn_fallback[ATT_ELEMS];
// bf16 hi/lo splits
__device__ __nv_bfloat16 g_xb0[CTX_ELEMS];
__device__ __nv_bfloat16 g_xb1[CTX_ELEMS];
__device__ __nv_bfloat16 g_wb0[3*Dn*Dn];
__device__ __nv_bfloat16 g_wb1[3*Dn*Dn];
__device__ __nv_bfloat16 g_qb0[CTX_ELEMS];
__device__ __nv_bfloat16 g_qb1[CTX_ELEMS];
__device__ __nv_bfloat16 g_kb0[CTX_ELEMS];
__device__ __nv_bfloat16 g_kb1[CTX_ELEMS];
__device__ __nv_bfloat16 g_vt0[CTX_ELEMS];   // V^T: [bh][dk=64][s=512]
__device__ __nv_bfloat16 g_vt1[CTX_ELEMS];

// ---------------- mma.sync bf16 (non-'a' tensor path, works on sm_103) -----
__device__ __forceinline__ void mma_bf16(float4& d, const uint32_t* a,
                                         uint32_t b0, uint32_t b1) {
    asm volatile(
        "mma.sync.aligned.m16n8k16.row.col.f32.bf16.bf16.f32 "
        "{%0,%1,%2,%3},{%4,%5,%6,%7},{%8,%9},{%0,%1,%2,%3};"
        : "+f"(d.x), "+f"(d.y), "+f"(d.z), "+f"(d.w)
        : "r"(a[0]), "r"(a[1]), "r"(a[2]), "r"(a[3]), "r"(b0), "r"(b1));
}

__device__ __forceinline__ void bsplit(float v, __nv_bfloat16& h, __nv_bfloat16& l) {
    h = __float2bfloat16(v);
    l = __float2bfloat16(v - __bfloat162float(h));
}
__device__ __forceinline__ uint32_t packbf(__nv_bfloat16 a, __nv_bfloat16 b) {
    __nv_bfloat162 t(a, b);
    return *(uint32_t*)&t;
}

// ---------------------------------------------------------------------------
// prep: bf16 hi/lo splits of X and the 3 weight matrices (single kernel)
// ---------------------------------------------------------------------------
#define XF4 (CTX_ELEMS/4)            // 4,194,304 float4 in X
#define WF4 (3*Dn*Dn/4)              // 786,432 float4 in W

__global__ __launch_bounds__(256) void prep_kernel(
    const float* __restrict__ X,
    const float* __restrict__ Wq, const float* __restrict__ Wk, const float* __restrict__ Wv)
{
    size_t i = (size_t)blockIdx.x * 256 + threadIdx.x;
    if (i < XF4) {
        float4 v = ((const float4*)X)[i];
        float f[4] = {v.x, v.y, v.z, v.w};
        __nv_bfloat16 b0[4], b1[4];
#pragma unroll
        for (int k = 0; k < 4; k++) bsplit(f[k], b0[k], b1[k]);
        ((uint32_t*)g_xb0)[i*2]   = packbf(b0[0], b0[1]);
        ((uint32_t*)g_xb0)[i*2+1] = packbf(b0[2], b0[3]);
        ((uint32_t*)g_xb1)[i*2]   = packbf(b1[0], b1[1]);
        ((uint32_t*)g_xb1)[i*2+1] = packbf(b1[2], b1[3]);
    } else {
        size_t j = i - XF4;
        if (j >= WF4) return;
        int z = (int)(j >> 18);
        const float* src = (z == 0) ? Wq : (z == 1) ? Wk : Wv;
        float4 v = ((const float4*)src)[j & 262143];
        float f[4] = {v.x, v.y, v.z, v.w};
        __nv_bfloat16 b0[4], b1[4];
#pragma unroll
        for (int k = 0; k < 4; k++) bsplit(f[k], b0[k], b1[k]);
        ((uint32_t*)g_wb0)[j*2]   = packbf(b0[0], b0[1]);
        ((uint32_t*)g_wb0)[j*2+1] = packbf(b0[2], b0[3]);
        ((uint32_t*)g_wb1)[j*2]   = packbf(b1[0], b1[1]);
        ((uint32_t*)g_wb1)[j*2+1] = packbf(b1[2], b1[3]);
    }
}

// ---------------------------------------------------------------------------
// QKV projection via mma.sync bf16x3: C = X @ W^T + bias
// Dead K/V tiles (batch-local row start >= length[b]) early-exit.
// ---------------------------------------------------------------------------
#define SA 20   // smem row stride in words

__global__ __launch_bounds__(256, 2) void qkv_mma_kernel(
    const float* __restrict__ bq, const float* __restrict__ bk, const float* __restrict__ bv,
    const int* __restrict__ length)
{
    __shared__ uint32_t As[2][128*SA];
    __shared__ uint32_t Bs[2][128*SA];

    const int tid  = threadIdx.x;
    const int wid  = tid >> 5;
    const int lane = tid & 31;
    const int gid  = lane >> 2;
    const int tig  = lane & 3;
    const int wm   = wid >> 1;
    const int wn   = wid & 1;
    const int z    = blockIdx.z;
    const int bm   = blockIdx.y * 128;
    const int bn   = blockIdx.x * 128;

    if (z >= 1) {
        if ((bm & 511) >= length[bm >> 9]) return;
    }

    const size_t zoff = (size_t)z * Dn * Dn;
    const __nv_bfloat16* w0p = g_wb0 + zoff;
    const __nv_bfloat16* w1p = g_wb1 + zoff;

    const int r0 = tid >> 3;
    const int c4 = tid & 7;

    float4 acc[2][8];
#pragma unroll
    for (int mt = 0; mt < 2; mt++)
#pragma unroll
        for (int nt = 0; nt < 8; nt++) acc[mt][nt] = make_float4(0.f, 0.f, 0.f, 0.f);

    uint2 areg[4], breg[4];
    {
        const __nv_bfloat16* a = g_xb0 + (size_t)bm * Dn;
        const __nv_bfloat16* w = w0p   + (size_t)bn * Dn;
#pragma unroll
        for (int j = 0; j < 4; j++) {
            int row = r0 + j*32;
            areg[j] = *(const uint2*)(a + (size_t)row*Dn + c4*4);
            breg[j] = *(const uint2*)(w + (size_t)row*Dn + c4*4);
        }
#pragma unroll
        for (int j = 0; j < 4; j++) {
            int row = r0 + j*32;
            int wo = row*SA + c4*2;
            *(uint2*)&As[0][wo] = areg[j];
            *(uint2*)&Bs[0][wo] = breg[j];
        }
    }
    __syncthreads();

    for (int it = 0; it < 96; it++) {
        const int cur = it & 1;
        if (it + 1 < 96) {
            int p  = (it + 1) >> 5;
            int kc = ((it + 1) & 31) * 32;
            const __nv_bfloat16* a = ((p == 2) ? g_xb1 : g_xb0) + (size_t)bm * Dn + kc;
            const __nv_bfloat16* w = ((p == 1) ? w1p  : w0p  ) + (size_t)bn * Dn + kc;
#pragma unroll
            for (int j = 0; j < 4; j++) {
                int row = r0 + j*32;
                areg[j] = *(const uint2*)(a + (size_t)row*Dn + c4*4);
                breg[j] = *(const uint2*)(w + (size_t)row*Dn + c4*4);
            }
        }
#pragma unroll
        for (int s = 0; s < 2; s++) {
            uint32_t af[2][4];
#pragma unroll
            for (int mt = 0; mt < 2; mt++) {
                int base = (wm*32 + mt*16 + gid)*SA + s*8 + tig;
                af[mt][0] = As[cur][base];
                af[mt][1] = As[cur][base + 8*SA];
                af[mt][2] = As[cur][base + 4];
                af[mt][3] = As[cur][base + 8*SA + 4];
            }
#pragma unroll
            for (int nt = 0; nt < 8; nt++) {
                int nb = (wn*64 + nt*8 + gid)*SA + s*8 + tig;
                uint32_t b0 = Bs[cur][nb];
                uint32_t b1 = Bs[cur][nb + 4];
                mma_bf16(acc[0][nt], af[0], b0, b1);
                mma_bf16(acc[1][nt], af[1], b0, b1);
            }
        }
        if (it + 1 < 96) {
            const int nxt = (it + 1) & 1;
#pragma unroll
            for (int j = 0; j < 4; j++) {
                int row = r0 + j*32;
                int wo = row*SA + c4*2;
                *(uint2*)&As[nxt][wo] = areg[j];
                *(uint2*)&Bs[nxt][wo] = breg[j];
            }
            __syncthreads();
        }
    }

    const float* bias = (z == 0) ? bq : (z == 1) ? bk : bv;
    if (z == 2) {
#pragma unroll
        for (int mt = 0; mt < 2; mt++) {
            int rowa = bm + wm*32 + mt*16 + gid;
            int rowb = rowa + 8;
            int ba = rowa >> 9, sa = rowa & 511;
            int bb2 = rowb >> 9, sb = rowb & 511;
#pragma unroll
            for (int nt = 0; nt < 8; nt++) {
                int feat = bn + wn*64 + nt*8 + tig*2;
                int h = feat >> 6, dk = feat & 63;
                float2 bv2 = *(const float2*)&bias[feat];
                float2 v0 = make_float2(acc[mt][nt].x + bv2.x, acc[mt][nt].y + bv2.y);
                float2 v1 = make_float2(acc[mt][nt].z + bv2.x, acc[mt][nt].w + bv2.y);
                *(float2*)&g_v[((size_t)((ba *Hn + h)*Sn + sa))*DKn + dk] = v0;
                *(float2*)&g_v[((size_t)((bb2*Hn + h)*Sn + sb))*DKn + dk] = v1;
            }
        }
    } else {
        __nv_bfloat16* o0 = (z == 0) ? g_qb0 : g_kb0;
        __nv_bfloat16* o1 = (z == 0) ? g_qb1 : g_kb1;
#pragma unroll
        for (int mt = 0; mt < 2; mt++) {
            int rowa = bm + wm*32 + mt*16 + gid;
            int rowb = rowa + 8;
            int ba = rowa >> 9, sa = rowa & 511;
            int bb2 = rowb >> 9, sb = rowb & 511;
#pragma unroll
            for (int nt = 0; nt < 8; nt++) {
                int feat = bn + wn*64 + nt*8 + tig*2;
                int h = feat >> 6, dk = feat & 63;
                float2 bv2 = *(const float2*)&bias[feat];
                float vx = acc[mt][nt].x + bv2.x, vy = acc[mt][nt].y + bv2.y;
                float vz = acc[mt][nt].z + bv2.x, vw = acc[mt][nt].w + bv2.y;
                __nv_bfloat16 hx,lx,hy,ly,hz,lz,hw,lw;
                bsplit(vx,hx,lx); bsplit(vy,hy,ly); bsplit(vz,hz,lz); bsplit(vw,hw,lw);
                size_t ia = ((size_t)((ba *Hn + h)*Sn + sa))*DKn + dk;
                size_t ib = ((size_t)((bb2*Hn + h)*Sn + sb))*DKn + dk;
                *(uint32_t*)&o0[ia] = packbf(hx,hy);
                *(uint32_t*)&o1[ia] = packbf(lx,ly);
                *(uint32_t*)&o0[ib] = packbf(hz,hw);
                *(uint32_t*)&o1[ib] = packbf(lz,lw);
            }
        }
    }
}

// ---------------------------------------------------------------------------
// vtrans: g_v fp32 [bh][s][64] -> bf16 hi/lo V^T [bh][64][512]
// ---------------------------------------------------------------------------
__global__ __launch_bounds__(256) void vtrans_kernel(const int* __restrict__ length)
{
    const int bh = blockIdx.y;
    const int s0 = blockIdx.x * 64;
    {
        int len = length[bh >> 4];
        int kmax = (len + 31) & ~31; if (kmax > Sn) kmax = Sn;
        if (s0 >= kmax) return;
    }
    __shared__ float T[64][65];
    const int tid = threadIdx.x;
#pragma unroll
    for (int j = 0; j < 4; j++) {
        int f = tid + j*256;
        int row = f >> 4, cc = (f & 15) * 4;
        float4 v = *(const float4*)&g_v[((size_t)bh*Sn + s0 + row)*DKn + cc];
        T[row][cc] = v.x; T[row][cc+1] = v.y; T[row][cc+2] = v.z; T[row][cc+3] = v.w;
    }
    __syncthreads();
#pragma unroll
    for (int j = 0; j < 8; j++) {
        int g = tid + j*256;
        int dk = g >> 5, sc = (g & 31) * 2;
        float va = T[sc][dk], vb = T[sc+1][dk];
        __nv_bfloat16 ha,la,hb,lb;
        bsplit(va,ha,la); bsplit(vb,hb,lb);
        size_t idx = ((size_t)bh*DKn + dk)*Sn + s0 + sc;
        *(uint32_t*)&g_vt0[idx] = packbf(ha,hb);
        *(uint32_t*)&g_vt1[idx] = packbf(la,lb);
    }
}

// ---------------------------------------------------------------------------
// Fused attention: one CTA owns a full (bh, 128q) row-block.
// Phase A (= R13 scores): e = exp(qk/8)*mask written unnormalized to attn,
//   complete rowsums -> smem invS. Masked strips zero-filled.
// Phase B (= R13 av): re-reads its own e (L2-hot), normalizes attn in place,
//   ctx = (E @ V) * inv. V^T tiles from gmem, register prefetch.
// ---------------------------------------------------------------------------
__global__ __launch_bounds__(256, 2) void attn_fused_kernel(
    const int* __restrict__ length, float* __restrict__ attn, float* __restrict__ ctx)
{
    __shared__ uint32_t SM[10240];   // A: As[2][2560]|Bs[2][2560]. B: As0|As1|Bs0|Bs1
    __shared__ float rs[128][2];
    __shared__ float invS[128];

    const int tid  = threadIdx.x;
    const int wid  = tid >> 5;
    const int lane = tid & 31;
    const int gid  = lane >> 2;
    const int tig  = lane & 3;
    const int wm   = wid >> 1;
    const int wn   = wid & 1;
    const int bh = blockIdx.y;
    const int b  = bh >> 4;
    const int h  = bh & 15;
    const int q0 = blockIdx.x * 128;

    const int len = length[b];
    int nsub = (len + 127) >> 7;
    if (nsub > 4) nsub = 4;
    const int total = nsub * 6;

    const int r0 = tid >> 3;
    const int c4 = tid & 7;

    // ======================= Phase A: scores =======================
    {
        uint32_t* pA = SM;          // 2 stages x 2560
        uint32_t* pB = SM + 5120;   // 2 stages x 2560

        const __nv_bfloat16* qs[2] = { g_qb0 + ((size_t)bh*Sn + q0)*DKn,
                                       g_qb1 + ((size_t)bh*Sn + q0)*DKn };
        const __nv_bfloat16* kb[2] = { g_kb0 + (size_t)bh*Sn*DKn,
                                       g_kb1 + (size_t)bh*Sn*DKn };
        const int pa[3]  = {0, 0, 1};
        const int pb3[3] = {0, 1, 0};

        float4 acc[2][8];
#pragma unroll
        for (int mt = 0; mt < 2; mt++)
#pragma unroll
            for (int nt = 0; nt < 8; nt++) acc[mt][nt] = make_float4(0.f, 0.f, 0.f, 0.f);
        float rp[2][2] = {{0.f, 0.f}, {0.f, 0.f}};

        uint2 areg[4], breg[4];
        {
            const __nv_bfloat16* a = qs[0];
            const __nv_bfloat16* w = kb[0];
#pragma unroll
            for (int j = 0; j < 4; j++) {
                int row = r0 + j*32;
                areg[j] = *(const uint2*)(a + (size_t)row*DKn + c4*4);
                breg[j] = *(const uint2*)(w + (size_t)row*DKn + c4*4);
            }
#pragma unroll
            for (int j = 0; j < 4; j++) {
                int row = r0 + j*32;
                int wo = row*SA + c4*2;
                *(uint2*)&pA[wo] = areg[j];
                *(uint2*)&pB[wo] = breg[j];
            }
        }
        __syncthreads();

        for (int gi = 0; gi < total; gi++) {
            const int cur = gi & 1;
            if (gi + 1 < total) {
                int g1  = gi + 1;
                int sub = g1 / 6;
                int qq  = g1 - sub*6;
                int p   = qq >> 1;
                int kc  = (qq & 1) * 32;
                const __nv_bfloat16* a = qs[pa[p]] + kc;
                const __nv_bfloat16* w = kb[pb3[p]] + (size_t)(sub << 7)*DKn + kc;
#pragma unroll
                for (int j = 0; j < 4; j++) {
                    int row = r0 + j*32;
                    areg[j] = *(const uint2*)(a + (size_t)row*DKn + c4*4);
                    breg[j] = *(const uint2*)(w + (size_t)row*DKn + c4*4);
                }
            }
#pragma unroll
            for (int s = 0; s < 2; s++) {
                uint32_t af[2][4];
#pragma unroll
                for (int mt = 0; mt < 2; mt++) {
                    int base = cur*2560 + (wm*32 + mt*16 + gid)*SA + s*8 + tig;
                    af[mt][0] = pA[base];
                    af[mt][1] = pA[base + 8*SA];
                    af[mt][2] = pA[base + 4];
                    af[mt][3] = pA[base + 8*SA + 4];
                }
#pragma unroll
                for (int nt = 0; nt < 8; nt++) {
                    int nb = cur*2560 + (wn*64 + nt*8 + gid)*SA + s*8 + tig;
                    uint32_t b0 = pB[nb];
                    uint32_t b1 = pB[nb + 4];
                    mma_bf16(acc[0][nt], af[0], b0, b1);
                    mma_bf16(acc[1][nt], af[1], b0, b1);
                }
            }
            if ((gi % 6) == 5) {
                const int k0 = (gi / 6) << 7;
#pragma unroll
                for (int mt = 0; mt < 2; mt++) {
                    int sa = q0 + wm*32 + mt*16 + gid;
                    int sb = sa + 8;
#pragma unroll
                    for (int nt = 0; nt < 8; nt++) {
                        int kc0 = k0 + wn*64 + nt*8 + tig*2;
                        float4 a = acc[mt][nt];
                        float ex = (kc0   < len) ? __expf(a.x * 0.125f) : 0.f;
                        float ey = (kc0+1 < len) ? __expf(a.y * 0.125f) : 0.f;
                        float ez = (kc0   < len) ? __expf(a.z * 0.125f) : 0.f;
                        float ew = (kc0+1 < len) ? __expf(a.w * 0.125f) : 0.f;
                        *(float2*)&attn[((size_t)bh*Sn + sa)*Sn + kc0] = make_float2(ex, ey);
                        *(float2*)&attn[((size_t)bh*Sn + sb)*Sn + kc0] = make_float2(ez, ew);
                        rp[mt][0] += ex + ey;
                        rp[mt][1] += ez + ew;
                        acc[mt][nt] = make_float4(0.f, 0.f, 0.f, 0.f);
                    }
                }
            }
            if (gi + 1 < total) {
                const int nxt = (gi + 1) & 1;
#pragma unroll
                for (int j = 0; j < 4; j++) {
                    int row = r0 + j*32;
                    int wo = nxt*2560 + row*SA + c4*2;
                    *(uint2*)&pA[wo] = areg[j];
                    *(uint2*)&pB[wo] = breg[j];
                }
                __syncthreads();
            }
        }

        // zero-fill fully masked strips
        for (int sub = nsub; sub < 4; sub++) {
            const int k0 = sub << 7;
            float4 z4 = make_float4(0.f, 0.f, 0.f, 0.f);
#pragma unroll
            for (int j = 0; j < 16; j++) {
                int f = tid + j*256;
                int row = f >> 5, cc = (f & 31) * 4;
                *(float4*)&attn[((size_t)bh*Sn + q0 + row)*Sn + k0 + cc] = z4;
            }
        }

        // rowsums -> invS
#pragma unroll
        for (int mt = 0; mt < 2; mt++) {
            rp[mt][0] += __shfl_xor_sync(0xffffffffu, rp[mt][0], 1);
            rp[mt][0] += __shfl_xor_sync(0xffffffffu, rp[mt][0], 2);
            rp[mt][1] += __shfl_xor_sync(0xffffffffu, rp[mt][1], 1);
            rp[mt][1] += __shfl_xor_sync(0xffffffffu, rp[mt][1], 2);
            if (tig == 0) {
                int ra = wm*32 + mt*16 + gid;
                rs[ra][wn]     = rp[mt][0];
                rs[ra + 8][wn] = rp[mt][1];
            }
        }
        __syncthreads();
        if (tid < 128)
            invS[tid] = 1.0f / (rs[tid][0] + rs[tid][1] + 1e-8f);
        // phase B's first __syncthreads orders invS + SM reuse
    }

    // ======================= Phase B: av =======================
    {
        uint32_t* As0 = SM;
        uint32_t* As1 = SM + 2560;
        uint32_t* Bs0 = SM + 5120;
        uint32_t* Bs1 = SM + 6400;

        float* Ah = attn + ((size_t)bh*Sn + q0) * Sn;
        const __nv_bfloat16* vt0 = g_vt0 + (size_t)bh * DKn * Sn;
        const __nv_bfloat16* vt1 = g_vt1 + (size_t)bh * DKn * Sn;

        int kmax = (len + 31) & ~31;
        if (kmax > Sn) kmax = Sn;

        float4 accB[8];
#pragma unroll
        for (int nt = 0; nt < 8; nt++) accB[nt] = make_float4(0.f, 0.f, 0.f, 0.f);

        // prefetch kc = 0 (L2-hot: this CTA just wrote these lines)
        float4 avr[4];
        uint2 b0r[2], b1r[2];
#pragma unroll
        for (int j = 0; j < 4; j++) {
            int f = tid + j*256;
            int row = f >> 3, cc = f & 7;
            avr[j] = *(const float4*)(Ah + (size_t)row*Sn + 0 + cc*4);
        }
#pragma unroll
        for (int j = 0; j < 2; j++) {
            int g = tid + j*256;
            int row = g >> 3, cc = g & 7;
            b0r[j] = *(const uint2*)(vt0 + (size_t)row*Sn + 0 + cc*4);
            b1r[j] = *(const uint2*)(vt1 + (size_t)row*Sn + 0 + cc*4);
        }

        for (int kc = 0; kc < kmax; kc += 32) {
            __syncthreads();   // orders invS/SM reuse (iter 0) and prev mma reads
#pragma unroll
            for (int j = 0; j < 4; j++) {
                int f = tid + j*256;
                int row = f >> 3, cc = f & 7;
                float iv = invS[row];
                float4 vv = avr[j];
                vv.x *= iv; vv.y *= iv; vv.z *= iv; vv.w *= iv;
                *(float4*)(Ah + (size_t)row*Sn + kc + cc*4) = vv;
                __nv_bfloat16 h0,l0,h1,l1,h2,l2,h3,l3;
                bsplit(vv.x,h0,l0); bsplit(vv.y,h1,l1); bsplit(vv.z,h2,l2); bsplit(vv.w,h3,l3);
                int wo = row*SA + cc*2;
                As0[wo]   = packbf(h0,h1); As0[wo+1] = packbf(h2,h3);
                As1[wo]   = packbf(l0,l1); As1[wo+1] = packbf(l2,l3);
            }
#pragma unroll
            for (int j = 0; j < 2; j++) {
                int g = tid + j*256;
                int row = g >> 3, cc = g & 7;
                int wo = row*SA + cc*2;
                *(uint2*)&Bs0[wo] = b0r[j];
                *(uint2*)&Bs1[wo] = b1r[j];
            }
            __syncthreads();

            if (kc + 32 < kmax) {
#pragma unroll
                for (int j = 0; j < 4; j++) {
                    int f = tid + j*256;
                    int row = f >> 3, cc = f & 7;
                    avr[j] = *(const float4*)(Ah + (size_t)row*Sn + kc + 32 + cc*4);
                }
#pragma unroll
                for (int j = 0; j < 2; j++) {
                    int g = tid + j*256;
                    int row = g >> 3, cc = g & 7;
                    b0r[j] = *(const uint2*)(vt0 + (size_t)row*Sn + kc + 32 + cc*4);
                    b1r[j] = *(const uint2*)(vt1 + (size_t)row*Sn + kc + 32 + cc*4);
                }
            }

#pragma unroll
            for (int s = 0; s < 2; s++) {
                uint32_t af0[4], af1[4];
                int base = (wid*16 + gid)*SA + s*8 + tig;
                af0[0] = As0[base];        af0[1] = As0[base + 8*SA];
                af0[2] = As0[base + 4];    af0[3] = As0[base + 8*SA + 4];
                af1[0] = As1[base];        af1[1] = As1[base + 8*SA];
                af1[2] = As1[base + 4];    af1[3] = As1[base + 8*SA + 4];
#pragma unroll
                for (int nt = 0; nt < 8; nt++) {
                    int nb = (nt*8 + gid)*SA + s*8 + tig;
                    uint32_t b00 = Bs0[nb], b01 = Bs0[nb + 4];
                    uint32_t b10 = Bs1[nb], b11 = Bs1[nb + 4];
                    mma_bf16(accB[nt], af0, b00, b01);   // a0*v0
                    mma_bf16(accB[nt], af0, b10, b11);   // a0*v1
                    mma_bf16(accB[nt], af1, b00, b01);   // a1*v0
                }
            }
        }

        int sa = q0 + wid*16 + gid;
        int sb = sa + 8;
#pragma unroll
        for (int nt = 0; nt < 8; nt++) {
            int dk = nt*8 + tig*2;
            *(float2*)&ctx[((size_t)(b*Sn + sa))*Dn + h*DKn + dk] = make_float2(accB[nt].x, accB[nt].y);
            *(float2*)&ctx[((size_t)(b*Sn + sb))*Dn + h*DKn + dk] = make_float2(accB[nt].z, accB[nt].w);
        }
    }
}

// ---------------------------------------------------------------------------
extern "C" void kernel_launch(void* const* d_in, const int* in_sizes, int n_in,
                              void* d_out, int out_size)
{
    const float* Q   = (const float*)d_in[0];
    const float* Wq  = (const float*)d_in[1];
    const float* bq  = (const float*)d_in[2];
    const float* Wk  = (const float*)d_in[3];
    const float* bk  = (const float*)d_in[4];
    const float* Wv  = (const float*)d_in[5];
    const float* bv  = (const float*)d_in[6];
    const int*   len = (const int*)d_in[7];

    float* ctx = (float*)d_out;
    float* attn;
    if ((size_t)out_size >= (size_t)CTX_ELEMS + ATT_ELEMS) {
        attn = ctx + CTX_ELEMS;   // tuple output: [context | attn]
    } else {
        void* p = nullptr;
        cudaGetSymbolAddress(&p, g_attn_fallback);
        attn = (float*)p;
    }

    // 0) bf16 hi/lo splits of inputs (single kernel)
    prep_kernel<<<dim3((XF4 + WF4 + 255)/256), 256>>>(Q, Wq, Wk, Wv);
    // 1) QKV projections (tensor cores); dead K/V tiles skipped
    qkv_mma_kernel<<<dim3(Dn/128, Mtot/128, 3), 256>>>(bq, bk, bv, len);
    // 1b) V^T bf16 splits (tiles beyond length skipped)
    vtrans_kernel<<<dim3(Sn/64, BH), 256>>>(len);
    // 2) fused scores + normalize + av (per-CTA row-block, L2-hot re-read)
    attn_fused_kernel<<<dim3(Sn/128, BH), 256>>>(len, attn, ctx);
}